// round 9
// baseline (speedup 1.0000x reference)
#include <cuda_runtime.h>
#include <math.h>
#include <cstdint>

#define HH 128
#define WW 128
#define HW (HH*WW)
#define CC 64
#define OO 64
#define BB 4
#define KK 9
#define VPAD 129

// Scratch (allocation-free rule: __device__ globals)
__device__ float4 g_wts[BB*KK*HW];        // per (b,k,pixel): 4 bilinear corner weights * mask
__device__ int4   g_offs[BB*KK*HW];       // per (b,k,pixel): 4 clamped corner plane-offsets
__device__ float  g_wt[KK*CC*OO];         // weight transposed to [k][c][o]
__device__ float  g_xm[(size_t)BB*HW*CC]; // x_main pixel-major [b][p][c]
__device__ float  g_wom[2*32*9*28];       // w_om pre-staged: [half][(cl*9+t)*28 + oc]
__device__ float  g_part[2*BB*28*HW];     // offset-conv partials [half][b][j][pix]

// ---- packed f32x2 helpers ----
__device__ __forceinline__ unsigned long long pk2(float lo, float hi) {
    unsigned long long r;
    asm("mov.b64 %0,{%1,%2};" : "=l"(r) : "f"(lo), "f"(hi));
    return r;
}
__device__ __forceinline__ void fma2(unsigned long long& d, unsigned long long a, unsigned long long b) {
    asm("fma.rn.f32x2 %0,%1,%2,%0;" : "+l"(d) : "l"(a), "l"(b));
}
__device__ __forceinline__ float2 up2(unsigned long long v) {
    float2 r;
    asm("mov.b64 {%0,%1},%2;" : "=f"(r.x), "=f"(r.y) : "l"(v));
    return r;
}
__device__ __forceinline__ float fast_tanh(float x) {
    float e = __expf(2.f * x);
    return 1.f - __fdividef(2.f, e + 1.f);
}
__device__ __forceinline__ float fast_sigmoid(float x) {
    return __fdividef(1.f, 1.f + __expf(-x));
}

// ---------------- kernel 0a: weight transpose [O][C][K] -> [K][C][O] ----------------
__global__ void k_wt_transpose(const float* __restrict__ w) {
    int i = blockIdx.x * 256 + threadIdx.x;
    if (i >= KK*CC*OO) return;
    int k = i >> 12;
    int r = i & 4095;
    int c = r >> 6;
    int o = r & 63;
    g_wt[i] = w[(o*CC + c)*KK + k];
}

// ---------------- kernel 0a': w_om pre-stage into smem-ready layout ----------------
__global__ void k_wom_prep(const float* __restrict__ w_om) {
    int i = blockIdx.x * 256 + threadIdx.x;
    if (i >= 2*32*9*28) return;
    int half = i / (32*9*28);
    int r = i - half*(32*9*28);
    int ct = r / 28;
    int oc = r - ct*28;
    int cl = ct / 9;
    int t  = ct - cl*9;
    float v = 0.f;
    if (oc < 27) v = w_om[(oc*CC + (half*32 + cl))*KK + t];
    g_wom[i] = v;
}

// ---------------- kernel 0b: x_main transpose [C][H][W] -> [H][W][C] ----------------
__global__ __launch_bounds__(256) void k_xm_transpose(const float* __restrict__ x) {
    __shared__ float s[64*68];
    const int tid = threadIdx.x;
    const int b = blockIdx.y;
    const int p0 = blockIdx.x << 6;
#pragma unroll
    for (int i = 0; i < 4; i++) {
        int t = (i << 8) + tid;
        int c = t >> 4, p4 = t & 15;
        float4 v = *(const float4*)(x + (((size_t)b*CC + c) << 14) + p0 + (p4 << 2));
        int base = (p4 << 2)*68 + c;
        s[base] = v.x; s[base+68] = v.y; s[base+136] = v.z; s[base+204] = v.w;
    }
    __syncthreads();
#pragma unroll
    for (int i = 0; i < 4; i++) {
        int t = (i << 8) + tid;
        int p = t >> 4, c4 = t & 15;
        float4 v = *(const float4*)&s[p*68 + (c4 << 2)];
        *(float4*)(g_xm + (((size_t)b << 14) + p0 + p)*CC + (c4 << 2)) = v;
    }
}

// ---------------- kernel 1a: offset-mask conv, half-channel partial ----------------
// blockIdx.z = b*2 + half; each block: 32 channels, 16x16 px, 2 px/thread.
__global__ __launch_bounds__(128) void k_offc(
        const float* __restrict__ x_extra) {
    __shared__ float ws[32*9*28];    // 32,256 B
    __shared__ float xt[4*18*20];    // 5,760 B
    const int tid = threadIdx.x;
    const int bz = blockIdx.z;
    const int b = bz >> 1;
    const int half = bz & 1;
    const int ty = tid >> 3;              // 0..15
    const int tx = tid & 7;               // 0..7
    const int h  = (blockIdx.y << 4) + ty;
    const int w0 = (blockIdx.x << 4) + (tx << 1);
    const int gy0 = (blockIdx.y << 4) - 1;
    const int gx0 = (blockIdx.x << 4) - 1;

    unsigned long long acc[2][14];
#pragma unroll
    for (int p = 0; p < 2; p++)
#pragma unroll
        for (int j = 0; j < 14; j++) acc[p][j] = 0ULL;

    const float* xb = x_extra + ((size_t)(b*CC) << 14) + ((size_t)(half << 5) << 14);

    {
        const float4* src = (const float4*)(g_wom + half*(32*9*28));
        float4* dst = (float4*)ws;
        for (int i = tid; i < 32*9*28/4; i += 128) dst[i] = src[i];
    }
    __syncthreads();

    for (int rnd = 0; rnd < 8; ++rnd) {
        if (rnd) __syncthreads();
        for (int idx = tid; idx < 4*324; idx += 128) {
            int cc = idx / 324;
            int rem = idx - cc*324;
            int rr = rem / 18, col = rem - rr*18;
            int gy = gy0 + rr, gx = gx0 + col;
            int c = (rnd << 2) + cc;
            xt[cc*360 + rr*20 + col] = ((unsigned)gy < HH && (unsigned)gx < WW)
                ? __ldg(xb + ((size_t)c << 14) + gy*WW + gx) : 0.f;
        }
        __syncthreads();

#pragma unroll
        for (int cl4 = 0; cl4 < 4; ++cl4) {
            const int cl = (rnd << 2) + cl4;
            float xp[3][4];
            const int base = cl4*360 + ty*20 + (tx << 1);
#pragma unroll
            for (int rr = 0; rr < 3; rr++) {
                float2 lo = *(const float2*)&xt[base + rr*20];
                float2 hi = *(const float2*)&xt[base + rr*20 + 2];
                xp[rr][0] = lo.x; xp[rr][1] = lo.y; xp[rr][2] = hi.x; xp[rr][3] = hi.y;
            }
#pragma unroll
            for (int t = 0; t < 9; t++) {
                const int tr = t/3, tc = t%3;
                const ulonglong2* wr = (const ulonglong2*)&ws[(cl*9 + t)*28];
                ulonglong2 q0 = wr[0], q1 = wr[1], q2 = wr[2];
                ulonglong2 q3 = wr[3], q4 = wr[4], q5 = wr[5], q6 = wr[6];
                unsigned long long xd0 = pk2(xp[tr][tc],     xp[tr][tc]);
                unsigned long long xd1 = pk2(xp[tr][tc + 1], xp[tr][tc + 1]);
                fma2(acc[0][0],  xd0, q0.x); fma2(acc[0][1],  xd0, q0.y);
                fma2(acc[0][2],  xd0, q1.x); fma2(acc[0][3],  xd0, q1.y);
                fma2(acc[0][4],  xd0, q2.x); fma2(acc[0][5],  xd0, q2.y);
                fma2(acc[0][6],  xd0, q3.x); fma2(acc[0][7],  xd0, q3.y);
                fma2(acc[0][8],  xd0, q4.x); fma2(acc[0][9],  xd0, q4.y);
                fma2(acc[0][10], xd0, q5.x); fma2(acc[0][11], xd0, q5.y);
                fma2(acc[0][12], xd0, q6.x); fma2(acc[0][13], xd0, q6.y);
                fma2(acc[1][0],  xd1, q0.x); fma2(acc[1][1],  xd1, q0.y);
                fma2(acc[1][2],  xd1, q1.x); fma2(acc[1][3],  xd1, q1.y);
                fma2(acc[1][4],  xd1, q2.x); fma2(acc[1][5],  xd1, q2.y);
                fma2(acc[1][6],  xd1, q3.x); fma2(acc[1][7],  xd1, q3.y);
                fma2(acc[1][8],  xd1, q4.x); fma2(acc[1][9],  xd1, q4.y);
                fma2(acc[1][10], xd1, q5.x); fma2(acc[1][11], xd1, q5.y);
                fma2(acc[1][12], xd1, q6.x); fma2(acc[1][13], xd1, q6.y);
            }
        }
    }

    // write 28 partials per pixel: g_part[((half*BB+b)*28 + j)*HW + pix]
    const size_t pbase = ((size_t)(half*BB + b)*28) << 14;
#pragma unroll
    for (int p = 0; p < 2; p++) {
        const int pix = h*WW + w0 + p;
#pragma unroll
        for (int j = 0; j < 14; j++) {
            float2 f = up2(acc[p][j]);
            g_part[pbase + ((size_t)(2*j)   << 14) + pix] = f.x;
            g_part[pbase + ((size_t)(2*j+1) << 14) + pix] = f.y;
        }
    }
}

// ---------------- kernel 1b: combine partials + transcendental/bilinear prep ----------------
__global__ __launch_bounds__(256) void k_offep(
        const float* __restrict__ pre_offset,
        const float* __restrict__ pre_sim,
        const float* __restrict__ b_om) {
    const int tid = threadIdx.x;
    const int b = blockIdx.y;
    const int pix = (blockIdx.x << 8) + tid;
    const int h = pix >> 7;
    const int w = pix & 127;

    const float* p0 = g_part + (((size_t)b*28) << 14) + pix;
    const float* p1 = g_part + (((size_t)(BB + b)*28) << 14) + pix;

    float a[28];
#pragma unroll
    for (int j = 0; j < 28; j++)
        a[j] = p0[(size_t)j << 14] + p1[(size_t)j << 14];

#pragma unroll
    for (int k = 0; k < 9; k++) {
        float ry = a[2*k]   + __ldg(b_om + 2*k);
        float rx = a[2*k+1] + __ldg(b_om + 2*k + 1);
        float rm = a[18+k]  + __ldg(b_om + 18 + k);
        int gi = (b*KK + k)*HW + pix;
        float poy = __ldg(pre_offset + 2*gi + 1);
        float pox = __ldg(pre_offset + 2*gi + 0);
        float ps  = __ldg(pre_sim + gi);

        float py = 10.f*fast_tanh(ry) + poy + (float)(h - 1) + (float)(k/3);
        float px = 10.f*fast_tanh(rx) + pox + (float)(w - 1) + (float)(k%3);
        float m  = fast_sigmoid(rm * ps);

        float fy = floorf(py), fx = floorf(px);
        float dy = py - fy,   dx = px - fx;
        int iy0 = (int)fy, ix0 = (int)fx;
        int iy1 = iy0 + 1, ix1 = ix0 + 1;
        bool vy0 = (unsigned)iy0 < HH, vy1 = (unsigned)iy1 < HH;
        bool vx0 = (unsigned)ix0 < WW, vx1 = (unsigned)ix1 < WW;

        float w00 = (vy0 && vx0) ? (1.f-dy)*(1.f-dx)*m : 0.f;
        float w01 = (vy0 && vx1) ? (1.f-dy)*dx*m       : 0.f;
        float w10 = (vy1 && vx0) ? dy*(1.f-dx)*m       : 0.f;
        float w11 = (vy1 && vx1) ? dy*dx*m             : 0.f;

        int cy0 = min(max(iy0, 0), HH-1), cy1 = min(max(iy1, 0), HH-1);
        int cx0 = min(max(ix0, 0), WW-1), cx1 = min(max(ix1, 0), WW-1);

        g_wts[gi]  = make_float4(w00, w01, w10, w11);
        g_offs[gi] = make_int4(cy0*WW + cx0, cy0*WW + cx1, cy1*WW + cx0, cy1*WW + cx1);
    }
}

// ---------------- kernel 2: coalesced gather + fma-balanced mini-GEMM (256 thr) ----------------
#define SM_V  0
#define SM_W  (CC*VPAD*4)                  // 33024
#define SM_WT (SM_W + CC*OO*4)             // +16384 = 49408
#define SM_OF (SM_WT + 128*16)             // +2048  = 51456
#define SM_SZ (SM_OF + 128*16)             // +2048  = 53504

__global__ __launch_bounds__(256) void k_main5(
        const float* __restrict__ bias,
        float* __restrict__ out) {
    extern __shared__ char sm[];
    float* v_s = (float*)(sm + SM_V);
    float* w_s = (float*)(sm + SM_W);
    float4* wt_s = (float4*)(sm + SM_WT);
    int4*   of_s = (int4*)(sm + SM_OF);

    const int tid = threadIdx.x;
    const int h = blockIdx.x;
    const int b = blockIdx.y;
    const int og = tid & 7;          // 8 o-groups of 8
    const int pg = tid >> 3;         // 32 px-groups of 4
    const float* xb = g_xm + ((size_t)b << 20);

    unsigned long long acc[16];      // acc[pi*4 + oj]: px pi(0..3) x o-pair oj(0..3)
#pragma unroll
    for (int j = 0; j < 16; j++) acc[j] = 0ULL;

    const int c4 = tid & 15;
    const int psub = tid >> 4;       // 0..15

    for (int k = 0; k < KK; ++k) {
        const int gibase = ((b*KK + k) << 14) + (h << 7);
        if (tid < 128) {
            wt_s[tid] = __ldg(&g_wts[gibase + tid]);
            of_s[tid] = __ldg(&g_offs[gibase + tid]);
        }
        {
            const float4* src = (const float4*)(g_wt + (k << 12));
            float4* dst = (float4*)w_s;
#pragma unroll
            for (int i = 0; i < 4; i++) dst[(i << 8) + tid] = src[(i << 8) + tid];
        }
        __syncthreads();

        // gather: 8 iterations, task (p = i*16 + psub, channels 4*c4..4*c4+3)
#pragma unroll 4
        for (int i = 0; i < 8; ++i) {
            int p = (i << 4) + psub;
            float4 wt = wt_s[p];
            int4   of = of_s[p];
            int cc = c4 << 2;
            float4 A0 = *(const float4*)(xb + ((size_t)of.x << 6) + cc);
            float4 A1 = *(const float4*)(xb + ((size_t)of.y << 6) + cc);
            float4 A2 = *(const float4*)(xb + ((size_t)of.z << 6) + cc);
            float4 A3 = *(const float4*)(xb + ((size_t)of.w << 6) + cc);
            v_s[(cc+0)*VPAD + p] = wt.x*A0.x + wt.y*A1.x + wt.z*A2.x + wt.w*A3.x;
            v_s[(cc+1)*VPAD + p] = wt.x*A0.y + wt.y*A1.y + wt.z*A2.y + wt.w*A3.y;
            v_s[(cc+2)*VPAD + p] = wt.x*A0.z + wt.y*A1.z + wt.z*A2.z + wt.w*A3.z;
            v_s[(cc+3)*VPAD + p] = wt.x*A0.w + wt.y*A1.w + wt.z*A2.w + wt.w*A3.w;
        }
        __syncthreads();

        // GEMM: acc2(p, o2) += dup(v[c][p]) * (w[c][2o], w[c][2o+1])
        // v_s rows are odd-padded (VPAD=129) -> scalar LDS only (no vector casts!)
#pragma unroll 4
        for (int c = 0; c < CC; ++c) {
            const float* vr = v_s + c*VPAD + (pg << 2);
            const float* wr = w_s + (c << 6) + (og << 3);
            ulonglong2 b01 = *(const ulonglong2*)(wr);
            ulonglong2 b23 = *(const ulonglong2*)(wr + 4);
            unsigned long long ad0 = pk2(vr[0], vr[0]);
            unsigned long long ad1 = pk2(vr[1], vr[1]);
            unsigned long long ad2 = pk2(vr[2], vr[2]);
            unsigned long long ad3 = pk2(vr[3], vr[3]);
            fma2(acc[0],  ad0, b01.x); fma2(acc[1],  ad0, b01.y);
            fma2(acc[2],  ad0, b23.x); fma2(acc[3],  ad0, b23.y);
            fma2(acc[4],  ad1, b01.x); fma2(acc[5],  ad1, b01.y);
            fma2(acc[6],  ad1, b23.x); fma2(acc[7],  ad1, b23.y);
            fma2(acc[8],  ad2, b01.x); fma2(acc[9],  ad2, b01.y);
            fma2(acc[10], ad2, b23.x); fma2(acc[11], ad2, b23.y);
            fma2(acc[12], ad3, b01.x); fma2(acc[13], ad3, b01.y);
            fma2(acc[14], ad3, b23.x); fma2(acc[15], ad3, b23.y);
        }
        __syncthreads();
    }

    // epilogue: 8 o's x 4 consecutive px per thread
    const int p0 = pg << 2;
    float* ob = out + ((size_t)(b*OO) << 14) + (h << 7) + p0;
#pragma unroll
    for (int oj = 0; oj < 4; ++oj) {
        int o = (og << 3) + (oj << 1);
        float be = __ldg(bias + o);
        float bo = __ldg(bias + o + 1);
        float2 s0 = up2(acc[0*4 + oj]);
        float2 s1 = up2(acc[1*4 + oj]);
        float2 s2 = up2(acc[2*4 + oj]);
        float2 s3 = up2(acc[3*4 + oj]);
        *(float4*)(ob + ((size_t)o << 14))       = make_float4(s0.x+be, s1.x+be, s2.x+be, s3.x+be);
        *(float4*)(ob + ((size_t)(o + 1) << 14)) = make_float4(s0.y+bo, s1.y+bo, s2.y+bo, s3.y+bo);
    }
}

extern "C" void kernel_launch(void* const* d_in, const int* in_sizes, int n_in,
                              void* d_out, int out_size) {
    const float* x_main     = (const float*)d_in[0];
    const float* x_extra    = (const float*)d_in[1];
    const float* pre_offset = (const float*)d_in[2];
    const float* pre_sim    = (const float*)d_in[3];
    const float* weight     = (const float*)d_in[4];
    const float* bias       = (const float*)d_in[5];
    const float* w_om       = (const float*)d_in[6];
    const float* b_om       = (const float*)d_in[7];
    float* out = (float*)d_out;

    cudaFuncSetAttribute(k_main5, cudaFuncAttributeMaxDynamicSharedMemorySize, SM_SZ);

    k_wt_transpose<<<(KK*CC*OO + 255)/256, 256>>>(weight);
    k_wom_prep<<<(2*32*9*28 + 255)/256, 256>>>(w_om);

    dim3 gt(HW/64, BB);
    k_xm_transpose<<<gt, 256>>>(x_main);

    dim3 g1(WW/16, HH/16, BB*2);
    k_offc<<<g1, 128>>>(x_extra);

    dim3 g1b(HW/256, BB);
    k_offep<<<g1b, 256>>>(pre_offset, pre_sim, b_om);

    dim3 g2(HH, BB);
    k_main5<<<g2, 256, SM_SZ>>>(bias, out);
}

// round 10
// speedup vs baseline: 1.2657x; 1.2657x over previous
#include <cuda_runtime.h>
#include <math.h>
#include <cstdint>

#define HH 128
#define WW 128
#define HW (HH*WW)
#define CC 64
#define OO 64
#define BB 4
#define KK 9
#define WPAD 72

// Scratch (allocation-free rule: __device__ globals)
__device__ float4 g_wts[BB*KK*HW];        // per (b,k,pixel): 4 bilinear corner weights * mask
__device__ int4   g_offs[BB*KK*HW];       // per (b,k,pixel): 4 clamped corner plane-offsets
__device__ float  g_xm[(size_t)BB*HW*CC]; // x_main pixel-major [b][p][c]
__device__ float  g_wom[2*32*9*28];       // w_om pre-staged: [half][(cl*9+t)*28 + oc]
__device__ uint32_t g_wth[KK*CC*WPAD];    // weight tf32-hi [k][c][o pad 72]
__device__ uint32_t g_wtl[KK*CC*WPAD];    // weight tf32-lo

// ---- packed f32x2 helpers (offset conv) ----
__device__ __forceinline__ unsigned long long pk2(float lo, float hi) {
    unsigned long long r;
    asm("mov.b64 %0,{%1,%2};" : "=l"(r) : "f"(lo), "f"(hi));
    return r;
}
__device__ __forceinline__ void fma2(unsigned long long& d, unsigned long long a, unsigned long long b) {
    asm("fma.rn.f32x2 %0,%1,%2,%0;" : "+l"(d) : "l"(a), "l"(b));
}
__device__ __forceinline__ float2 up2(unsigned long long v) {
    float2 r;
    asm("mov.b64 {%0,%1},%2;" : "=f"(r.x), "=f"(r.y) : "l"(v));
    return r;
}
// ---- tf32 helpers ----
__device__ __forceinline__ uint32_t to_tf32(float v) {
    uint32_t r;
    asm("cvt.rna.tf32.f32 %0,%1;" : "=r"(r) : "f"(v));
    return r;
}
__device__ __forceinline__ void mma_tf32(float* d, const uint32_t* a, const uint32_t* b) {
    asm volatile(
        "mma.sync.aligned.m16n8k8.row.col.f32.tf32.tf32.f32 "
        "{%0,%1,%2,%3}, {%4,%5,%6,%7}, {%8,%9}, {%0,%1,%2,%3};"
        : "+f"(d[0]), "+f"(d[1]), "+f"(d[2]), "+f"(d[3])
        : "r"(a[0]), "r"(a[1]), "r"(a[2]), "r"(a[3]), "r"(b[0]), "r"(b[1]));
}

// ---------------- kernel 0a: weight split [O][C][K] -> tf32 hi/lo [k][c][o pad72] ----------------
__global__ void k_wtf_prep(const float* __restrict__ w) {
    int i = blockIdx.x * 256 + threadIdx.x;
    if (i >= KK*CC*WPAD) return;
    int k = i / (CC*WPAD);
    int r = i - k*(CC*WPAD);
    int c = r / WPAD;
    int o = r - c*WPAD;
    float v = (o < OO) ? w[(o*CC + c)*KK + k] : 0.f;
    uint32_t hi = to_tf32(v);
    float lo = v - __uint_as_float(hi);
    g_wth[i] = hi;
    g_wtl[i] = to_tf32(lo);
}

// ---------------- kernel 0a': w_om pre-stage into smem-ready layout ----------------
__global__ void k_wom_prep(const float* __restrict__ w_om) {
    int i = blockIdx.x * 256 + threadIdx.x;
    if (i >= 2*32*9*28) return;
    int half = i / (32*9*28);
    int r = i - half*(32*9*28);
    int ct = r / 28;
    int oc = r - ct*28;
    int cl = ct / 9;
    int t  = ct - cl*9;
    float v = 0.f;
    if (oc < 27) v = w_om[(oc*CC + (half*32 + cl))*KK + t];
    g_wom[i] = v;
}

// ---------------- kernel 0b: x_main transpose [C][H][W] -> [H][W][C] ----------------
__global__ __launch_bounds__(256) void k_xm_transpose(const float* __restrict__ x) {
    __shared__ float s[64*68];
    const int tid = threadIdx.x;
    const int b = blockIdx.y;
    const int p0 = blockIdx.x << 6;
#pragma unroll
    for (int i = 0; i < 4; i++) {
        int t = (i << 8) + tid;
        int c = t >> 4, p4 = t & 15;
        float4 v = *(const float4*)(x + (((size_t)b*CC + c) << 14) + p0 + (p4 << 2));
        int base = (p4 << 2)*68 + c;
        s[base] = v.x; s[base+68] = v.y; s[base+136] = v.z; s[base+204] = v.w;
    }
    __syncthreads();
#pragma unroll
    for (int i = 0; i < 4; i++) {
        int t = (i << 8) + tid;
        int p = t >> 4, c4 = t & 15;
        float4 v = *(const float4*)&s[p*68 + (c4 << 2)];
        *(float4*)(g_xm + (((size_t)b << 14) + p0 + p)*CC + (c4 << 2)) = v;
    }
}

// ---------------- kernel 1: offset-mask conv + bilinear prep (R7 form, measured 84.7us) ----------------
__global__ __launch_bounds__(128) void k_offset3(
        const float* __restrict__ x_extra,
        const float* __restrict__ pre_offset,
        const float* __restrict__ pre_sim,
        const float* __restrict__ b_om) {
    __shared__ float ws[32*9*28];
    __shared__ float xt[4*18*20];
    const int tid = threadIdx.x;
    const int b = blockIdx.z;
    const int ty = tid >> 3;
    const int tx = tid & 7;
    const int h  = (blockIdx.y << 4) + ty;
    const int w0 = (blockIdx.x << 4) + (tx << 1);
    const int gy0 = (blockIdx.y << 4) - 1;
    const int gx0 = (blockIdx.x << 4) - 1;

    unsigned long long acc[2][14];
#pragma unroll
    for (int p = 0; p < 2; p++)
#pragma unroll
        for (int j = 0; j < 14; j++) acc[p][j] = 0ULL;

    const float* xb = x_extra + (size_t)b*CC*HW;

    for (int phase = 0; phase < 2; ++phase) {
        __syncthreads();
        {
            const float4* src = (const float4*)(g_wom + phase*(32*9*28));
            float4* dst = (float4*)ws;
            for (int i = tid; i < 32*9*28/4; i += 128) dst[i] = src[i];
        }
        __syncthreads();

        for (int rnd = 0; rnd < 8; ++rnd) {
            if (rnd) __syncthreads();
            for (int idx = tid; idx < 4*324; idx += 128) {
                int cc = idx / 324;
                int rem = idx - cc*324;
                int rr = rem / 18, col = rem - rr*18;
                int gy = gy0 + rr, gx = gx0 + col;
                int c = (phase << 5) + (rnd << 2) + cc;
                xt[cc*360 + rr*20 + col] = ((unsigned)gy < HH && (unsigned)gx < WW)
                    ? __ldg(xb + ((size_t)c << 14) + gy*WW + gx) : 0.f;
            }
            __syncthreads();

#pragma unroll
            for (int cl4 = 0; cl4 < 4; ++cl4) {
                const int cl = (rnd << 2) + cl4;
                float xp[3][4];
                const int base = cl4*360 + ty*20 + (tx << 1);
#pragma unroll
                for (int rr = 0; rr < 3; rr++) {
                    float2 lo = *(const float2*)&xt[base + rr*20];
                    float2 hi = *(const float2*)&xt[base + rr*20 + 2];
                    xp[rr][0] = lo.x; xp[rr][1] = lo.y; xp[rr][2] = hi.x; xp[rr][3] = hi.y;
                }
#pragma unroll
                for (int t = 0; t < 9; t++) {
                    const int tr = t/3, tc = t%3;
                    const ulonglong2* wr = (const ulonglong2*)&ws[(cl*9 + t)*28];
                    ulonglong2 q0 = wr[0], q1 = wr[1], q2 = wr[2];
                    ulonglong2 q3 = wr[3], q4 = wr[4], q5 = wr[5], q6 = wr[6];
                    unsigned long long xd0 = pk2(xp[tr][tc],     xp[tr][tc]);
                    unsigned long long xd1 = pk2(xp[tr][tc + 1], xp[tr][tc + 1]);
                    fma2(acc[0][0],  xd0, q0.x); fma2(acc[0][1],  xd0, q0.y);
                    fma2(acc[0][2],  xd0, q1.x); fma2(acc[0][3],  xd0, q1.y);
                    fma2(acc[0][4],  xd0, q2.x); fma2(acc[0][5],  xd0, q2.y);
                    fma2(acc[0][6],  xd0, q3.x); fma2(acc[0][7],  xd0, q3.y);
                    fma2(acc[0][8],  xd0, q4.x); fma2(acc[0][9],  xd0, q4.y);
                    fma2(acc[0][10], xd0, q5.x); fma2(acc[0][11], xd0, q5.y);
                    fma2(acc[0][12], xd0, q6.x); fma2(acc[0][13], xd0, q6.y);
                    fma2(acc[1][0],  xd1, q0.x); fma2(acc[1][1],  xd1, q0.y);
                    fma2(acc[1][2],  xd1, q1.x); fma2(acc[1][3],  xd1, q1.y);
                    fma2(acc[1][4],  xd1, q2.x); fma2(acc[1][5],  xd1, q2.y);
                    fma2(acc[1][6],  xd1, q3.x); fma2(acc[1][7],  xd1, q3.y);
                    fma2(acc[1][8],  xd1, q4.x); fma2(acc[1][9],  xd1, q4.y);
                    fma2(acc[1][10], xd1, q5.x); fma2(acc[1][11], xd1, q5.y);
                    fma2(acc[1][12], xd1, q6.x); fma2(acc[1][13], xd1, q6.y);
                }
            }
        }
    }

#pragma unroll
    for (int p = 0; p < 2; p++) {
        const int wp_ = w0 + p;
        const int pix = h*WW + wp_;
        float a[28];
#pragma unroll
        for (int j = 0; j < 14; j++) {
            float2 f = up2(acc[p][j]);
            a[2*j] = f.x; a[2*j+1] = f.y;
        }
#pragma unroll
        for (int k = 0; k < 9; k++) {
            float ry = a[2*k]   + __ldg(b_om + 2*k);
            float rx = a[2*k+1] + __ldg(b_om + 2*k + 1);
            float rm = a[18+k]  + __ldg(b_om + 18 + k);
            int gi = (b*KK + k)*HW + pix;
            float poy = __ldg(pre_offset + 2*gi + 1);
            float pox = __ldg(pre_offset + 2*gi + 0);
            float ps  = __ldg(pre_sim + gi);

            float py = 10.f*tanhf(ry) + poy + (float)(h - 1) + (float)(k/3);
            float px = 10.f*tanhf(rx) + pox + (float)(wp_ - 1) + (float)(k%3);
            float m  = 1.f / (1.f + expf(-(rm * ps)));

            float fy = floorf(py), fx = floorf(px);
            float dy = py - fy,   dx = px - fx;
            int iy0 = (int)fy, ix0 = (int)fx;
            int iy1 = iy0 + 1, ix1 = ix0 + 1;
            bool vy0 = (unsigned)iy0 < HH, vy1 = (unsigned)iy1 < HH;
            bool vx0 = (unsigned)ix0 < WW, vx1 = (unsigned)ix1 < WW;

            float w00 = (vy0 && vx0) ? (1.f-dy)*(1.f-dx)*m : 0.f;
            float w01 = (vy0 && vx1) ? (1.f-dy)*dx*m       : 0.f;
            float w10 = (vy1 && vx0) ? dy*(1.f-dx)*m       : 0.f;
            float w11 = (vy1 && vx1) ? dy*dx*m             : 0.f;

            int cy0 = min(max(iy0, 0), HH-1), cy1 = min(max(iy1, 0), HH-1);
            int cx0 = min(max(ix0, 0), WW-1), cx1 = min(max(ix1, 0), WW-1);

            g_wts[gi]  = make_float4(w00, w01, w10, w11);
            g_offs[gi] = make_int4(cy0*WW + cx0, cy0*WW + cx1, cy1*WW + cx0, cy1*WW + cx1);
        }
    }
}

// ---------------- kernel 2: gather -> tf32 hi/lo -> mma.sync (HMMA) ----------------
// Block = 128 threads = 4 warps, tile = one image row (128 px) x 64 o.
// Warp w: pixels [32w, 32w+32) x all 64 o. 3-pass tf32 split per k-chunk.
// smem (bytes):
#define SM_VH 0
#define SM_VL (SM_VH + 128*WPAD*4)     // 36864
#define SM_WH (SM_VL + 128*WPAD*4)     // 73728
#define SM_WL (SM_WH + CC*WPAD*4)      // 92160
#define SM_WT (SM_WL + CC*WPAD*4)      // 110592
#define SM_OF (SM_WT + 128*16)         // 112640
#define SM_SZ (SM_OF + 128*16)         // 114688

__global__ __launch_bounds__(128) void k_main6(
        const float* __restrict__ bias,
        float* __restrict__ out) {
    extern __shared__ char sm[];
    uint32_t* vh = (uint32_t*)(sm + SM_VH);
    uint32_t* vl = (uint32_t*)(sm + SM_VL);
    uint32_t* wh = (uint32_t*)(sm + SM_WH);
    uint32_t* wl = (uint32_t*)(sm + SM_WL);
    float4*   wt_s = (float4*)(sm + SM_WT);
    int4*     of_s = (int4*)(sm + SM_OF);

    const int tid = threadIdx.x;
    const int h = blockIdx.x;
    const int b = blockIdx.y;
    const int warp = tid >> 5;
    const int lane = tid & 31;
    const int g = lane >> 2;          // groupID
    const int tig = lane & 3;         // threadID in group
    const int pb = warp << 5;         // 32-px band per warp
    const float* xb = g_xm + ((size_t)b << 20);

    float d[2][8][4];
#pragma unroll
    for (int m = 0; m < 2; m++)
#pragma unroll
        for (int n = 0; n < 8; n++)
#pragma unroll
            for (int j = 0; j < 4; j++) d[m][n][j] = 0.f;

    const int c4 = tid & 15;
    const int psub = tid >> 4;

    for (int k = 0; k < KK; ++k) {
        // stage bilinear prep + weight hi/lo planes
        const int gibase = ((b*KK + k) << 14) + (h << 7);
        wt_s[tid] = __ldg(&g_wts[gibase + tid]);
        of_s[tid] = __ldg(&g_offs[gibase + tid]);
        {
            const float4* sh = (const float4*)(g_wth + k*CC*WPAD);
            const float4* sl = (const float4*)(g_wtl + k*CC*WPAD);
            float4* dh = (float4*)wh;
            float4* dl = (float4*)wl;
#pragma unroll
            for (int i = 0; i < 9; i++) {
                dh[(i << 7) + tid] = sh[(i << 7) + tid];
                dl[(i << 7) + tid] = sl[(i << 7) + tid];
            }
        }
        __syncthreads();

        // gather + tf32 split: task (p = i*8 + psub, channels 4c4..4c4+3)
#pragma unroll 4
        for (int i = 0; i < 16; ++i) {
            int p = (i << 3) + psub;
            float4 wt = wt_s[p];
            int4   of = of_s[p];
            int cc = c4 << 2;
            float4 A0 = *(const float4*)(xb + ((size_t)of.x << 6) + cc);
            float4 A1 = *(const float4*)(xb + ((size_t)of.y << 6) + cc);
            float4 A2 = *(const float4*)(xb + ((size_t)of.z << 6) + cc);
            float4 A3 = *(const float4*)(xb + ((size_t)of.w << 6) + cc);
            float v0 = wt.x*A0.x + wt.y*A1.x + wt.z*A2.x + wt.w*A3.x;
            float v1 = wt.x*A0.y + wt.y*A1.y + wt.z*A2.y + wt.w*A3.y;
            float v2 = wt.x*A0.z + wt.y*A1.z + wt.z*A2.z + wt.w*A3.z;
            float v3 = wt.x*A0.w + wt.y*A1.w + wt.z*A2.w + wt.w*A3.w;
            uint4 hh, ll;
            hh.x = to_tf32(v0); ll.x = to_tf32(v0 - __uint_as_float(hh.x));
            hh.y = to_tf32(v1); ll.y = to_tf32(v1 - __uint_as_float(hh.y));
            hh.z = to_tf32(v2); ll.z = to_tf32(v2 - __uint_as_float(hh.z));
            hh.w = to_tf32(v3); ll.w = to_tf32(v3 - __uint_as_float(hh.w));
            ((uint4*)vh)[p*18 + c4] = hh;   // word addr p*72 + 4*c4
            ((uint4*)vl)[p*18 + c4] = ll;
        }
        __syncthreads();

        // MMA: 8 ksteps x (2 M-tiles x 8 N-tiles) x 3 passes
#pragma unroll 2
        for (int kk = 0; kk < 8; ++kk) {
            const int kb = kk << 3;
            uint32_t ah[2][4], al[2][4];
#pragma unroll
            for (int m = 0; m < 2; m++) {
                int r0 = pb + (m << 4) + g;
                ah[m][0] = vh[r0*WPAD + kb + tig];
                ah[m][1] = vh[(r0 + 8)*WPAD + kb + tig];
                ah[m][2] = vh[r0*WPAD + kb + tig + 4];
                ah[m][3] = vh[(r0 + 8)*WPAD + kb + tig + 4];
                al[m][0] = vl[r0*WPAD + kb + tig];
                al[m][1] = vl[(r0 + 8)*WPAD + kb + tig];
                al[m][2] = vl[r0*WPAD + kb + tig + 4];
                al[m][3] = vl[(r0 + 8)*WPAD + kb + tig + 4];
            }
            uint32_t bh[8][2], bl[8][2];
#pragma unroll
            for (int n = 0; n < 8; n++) {
                int col = (n << 3) + g;
                bh[n][0] = wh[(kb + tig)*WPAD + col];
                bh[n][1] = wh[(kb + tig + 4)*WPAD + col];
                bl[n][0] = wl[(kb + tig)*WPAD + col];
                bl[n][1] = wl[(kb + tig + 4)*WPAD + col];
            }
#pragma unroll
            for (int m = 0; m < 2; m++)
#pragma unroll
                for (int n = 0; n < 8; n++) {
                    mma_tf32(d[m][n], ah[m], bh[n]);
                    mma_tf32(d[m][n], ah[m], bl[n]);
                    mma_tf32(d[m][n], al[m], bh[n]);
                }
        }
        __syncthreads();
    }

    // epilogue: d[m][n][j]: row=pixel pb+m*16+g(+8), col=o=8n+2tig(+1)
    float* ob = out + ((size_t)(b*OO) << 14) + (h << 7);
#pragma unroll
    for (int m = 0; m < 2; m++) {
        int p0 = pb + (m << 4) + g;
#pragma unroll
        for (int n = 0; n < 8; n++) {
            int o0 = (n << 3) + (tig << 1);
            float b0 = __ldg(bias + o0);
            float b1 = __ldg(bias + o0 + 1);
            ob[((size_t)o0       << 14) + p0]     = d[m][n][0] + b0;
            ob[((size_t)(o0 + 1) << 14) + p0]     = d[m][n][1] + b1;
            ob[((size_t)o0       << 14) + p0 + 8] = d[m][n][2] + b0;
            ob[((size_t)(o0 + 1) << 14) + p0 + 8] = d[m][n][3] + b1;
        }
    }
}

extern "C" void kernel_launch(void* const* d_in, const int* in_sizes, int n_in,
                              void* d_out, int out_size) {
    const float* x_main     = (const float*)d_in[0];
    const float* x_extra    = (const float*)d_in[1];
    const float* pre_offset = (const float*)d_in[2];
    const float* pre_sim    = (const float*)d_in[3];
    const float* weight     = (const float*)d_in[4];
    const float* bias       = (const float*)d_in[5];
    const float* w_om       = (const float*)d_in[6];
    const float* b_om       = (const float*)d_in[7];
    float* out = (float*)d_out;

    cudaFuncSetAttribute(k_main6, cudaFuncAttributeMaxDynamicSharedMemorySize, SM_SZ);

    k_wtf_prep<<<(KK*CC*WPAD + 255)/256, 256>>>(weight);
    k_wom_prep<<<(2*32*9*28 + 255)/256, 256>>>(w_om);

    dim3 gt(HW/64, BB);
    k_xm_transpose<<<gt, 256>>>(x_main);

    dim3 g1(WW/16, HH/16, BB);
    k_offset3<<<g1, 128>>>(x_extra, pre_offset, pre_sim, b_om);

    dim3 g2(HH, BB);
    k_main6<<<g2, 128, SM_SZ>>>(bias, out);
}